// round 9
// baseline (speedup 1.0000x reference)
#include <cuda_runtime.h>
#include <cstdint>

#define NNODES 50000
#define NEDGES 800000
#define ETOT   850000
#define FIN    128
#define H1     4
#define D1     256   // H1*C1
#define D2     64
#define DAGG   512   // H1*FIN
#define NEG_SLOPE 0.2f
#define NBLK_SCAN 196   // ceil(50000/256)

// ---------------- scratch (static device globals) ---------------------------
static __device__ float g_aggx[NNODES * DAGG];  // tf32-bit floats
static __device__ float g_xl2 [NNODES * D2];
static __device__ float g_ws1 [FIN * H1];
static __device__ float g_wd1 [FIN * H1];
static __device__ float g_as1 [NNODES * H1];
static __device__ float g_ad1 [NNODES * H1];
static __device__ float g_as2 [NNODES];
static __device__ float g_ad2 [NNODES];
static __device__ int   g_cnt [NNODES];
static __device__ int   g_rowptr[NNODES + 1];
static __device__ int   g_wptr[NNODES];
static __device__ int   g_bsum[256];
static __device__ int   g_boff[256];
static __device__ int   g_srcs[ETOT];

__device__ __forceinline__ void edge_nodes(const int* __restrict__ ei,
                                           int e, int& s, int& d) {
    if (e < NEDGES) { s = ei[e]; d = ei[NEDGES + e]; }
    else            { s = e - NEDGES; d = s; }
}

__device__ __forceinline__ uint32_t f2tf(float f) {
    uint32_t u;
    asm("cvt.rna.tf32.f32 %0, %1;" : "=r"(u) : "f"(f));
    return u;
}

__device__ __forceinline__ void mma_tf32(float c[4], const uint32_t a[4],
                                         const uint32_t b[2]) {
    asm volatile(
        "mma.sync.aligned.m16n8k8.row.col.f32.tf32.tf32.f32 "
        "{%0,%1,%2,%3}, {%4,%5,%6,%7}, {%8,%9}, {%0,%1,%2,%3};"
        : "+f"(c[0]), "+f"(c[1]), "+f"(c[2]), "+f"(c[3])
        : "r"(a[0]), "r"(a[1]), "r"(a[2]), "r"(a[3]), "r"(b[0]), "r"(b[1]));
}

// ================= CSR build =================================================
__global__ void zero_cnt(int* __restrict__ cnt) {
    int i = blockIdx.x * blockDim.x + threadIdx.x;
    if (i < NNODES) cnt[i] = 0;
}

__global__ void hist_kernel(const int* __restrict__ ei, int* __restrict__ cnt) {
    int e = blockIdx.x * blockDim.x + threadIdx.x;
    if (e >= ETOT) return;
    int s, d; edge_nodes(ei, e, s, d);
    atomicAdd(&cnt[d], 1);
}

__global__ void scan1_kernel(const int* __restrict__ cnt,
                             int* __restrict__ rowptr, int* __restrict__ bsum) {
    __shared__ int sm[256];
    int tid = threadIdx.x;
    int i = blockIdx.x * 256 + tid;
    int val = (i < NNODES) ? cnt[i] : 0;
    sm[tid] = val;
    __syncthreads();
    #pragma unroll
    for (int off = 1; off < 256; off <<= 1) {
        int t = (tid >= off) ? sm[tid - off] : 0;
        __syncthreads();
        sm[tid] += t;
        __syncthreads();
    }
    if (i < NNODES) rowptr[i] = sm[tid] - val;
    if (tid == 255) bsum[blockIdx.x] = sm[tid];
}

__global__ void scan2_kernel(int* __restrict__ bsum, int* __restrict__ boff) {
    __shared__ int sm[256];
    int tid = threadIdx.x;
    int val = (tid < NBLK_SCAN) ? bsum[tid] : 0;
    sm[tid] = val;
    __syncthreads();
    #pragma unroll
    for (int off = 1; off < 256; off <<= 1) {
        int t = (tid >= off) ? sm[tid - off] : 0;
        __syncthreads();
        sm[tid] += t;
        __syncthreads();
    }
    boff[tid] = sm[tid] - val;
}

__global__ void scan3_kernel(int* __restrict__ rowptr, const int* __restrict__ boff,
                             int* __restrict__ wptr) {
    int i = blockIdx.x * blockDim.x + threadIdx.x;
    if (i < NNODES) {
        int r = rowptr[i] + boff[i >> 8];
        rowptr[i] = r;
        wptr[i]   = r;
    }
    if (i == 0) rowptr[NNODES] = ETOT;
}

__global__ void scatter_kernel(const int* __restrict__ ei, int* __restrict__ wptr,
                               int* __restrict__ srcs) {
    int e = blockIdx.x * blockDim.x + threadIdx.x;
    if (e >= ETOT) return;
    int s, d; edge_nodes(ei, e, s, d);
    srcs[atomicAdd(&wptr[d], 1)] = s;
}

// ================= layer-1 attention weight precompute =======================
__global__ void w1prep_kernel(const float* __restrict__ W1,
                              const float* __restrict__ a_s,
                              const float* __restrict__ a_d,
                              float* __restrict__ ws, float* __restrict__ wd) {
    int t = threadIdx.x;              // 512 threads
    int c = t >> 2, h = t & 3;
    float accs = 0.f, accd = 0.f;
    #pragma unroll 8
    for (int j = 0; j < 64; j++) {
        float w = W1[c * D1 + h * 64 + j];
        accs += w * a_s[h * 64 + j];
        accd += w * a_d[h * 64 + j];
    }
    ws[c * 4 + h] = accs;
    wd[c * 4 + h] = accd;
}

// ================= per-node attention coefficients ===========================
__global__ void alpha1_kernel(const float* __restrict__ x,
                              const float* __restrict__ ws,
                              const float* __restrict__ wd,
                              float* __restrict__ asrc, float* __restrict__ adst) {
    int w = (blockIdx.x * blockDim.x + threadIdx.x) >> 5;
    int lane = threadIdx.x & 31;
    if (w >= NNODES) return;
    const float* row = x + (long)w * FIN;
    float ps[4] = {}, pd[4] = {};
    #pragma unroll
    for (int j = 0; j < 4; j++) {
        int c = lane + j * 32;
        float v = row[c];
        float4 a = *(const float4*)(ws + c * 4);
        float4 b = *(const float4*)(wd + c * 4);
        ps[0] += v * a.x; ps[1] += v * a.y; ps[2] += v * a.z; ps[3] += v * a.w;
        pd[0] += v * b.x; pd[1] += v * b.y; pd[2] += v * b.z; pd[3] += v * b.w;
    }
    #pragma unroll
    for (int off = 16; off; off >>= 1) {
        #pragma unroll
        for (int h = 0; h < 4; h++) {
            ps[h] += __shfl_xor_sync(0xFFFFFFFFu, ps[h], off);
            pd[h] += __shfl_xor_sync(0xFFFFFFFFu, pd[h], off);
        }
    }
    if (lane == 0) {
        *(float4*)(asrc + w * 4) = make_float4(ps[0], ps[1], ps[2], ps[3]);
        *(float4*)(adst + w * 4) = make_float4(pd[0], pd[1], pd[2], pd[3]);
    }
}

__global__ void alpha2_kernel(const float* __restrict__ xl,
                              const float* __restrict__ att_s,
                              const float* __restrict__ att_d,
                              float* __restrict__ asrc, float* __restrict__ adst) {
    int w = (blockIdx.x * blockDim.x + threadIdx.x) >> 5;
    int lane = threadIdx.x & 31;
    if (w >= NNODES) return;
    const float* row = xl + (long)w * D2;
    float v0 = row[lane], v1 = row[lane + 32];
    float ps = v0 * att_s[lane] + v1 * att_s[lane + 32];
    float pd = v0 * att_d[lane] + v1 * att_d[lane + 32];
    #pragma unroll
    for (int off = 16; off; off >>= 1) {
        ps += __shfl_xor_sync(0xFFFFFFFFu, ps, off);
        pd += __shfl_xor_sync(0xFFFFFFFFu, pd, off);
    }
    if (lane == 0) { asrc[w] = ps; adst[w] = pd; }
}

// ================= gather layer1 (input space, writes tf32 bits) =============
__global__ __launch_bounds__(256) void gather1_kernel(
    const int* __restrict__ rowptr, const int* __restrict__ srcs,
    const float* __restrict__ asrc, const float* __restrict__ adst,
    const float* __restrict__ x, float* __restrict__ aggx) {
    __shared__ int    sm_s [8][32];
    __shared__ float4 sm_ex[8][32];
    int wslot = threadIdx.x >> 5;
    int node = blockIdx.x * 8 + wslot;
    if (node >= NNODES) return;
    int lane = threadIdx.x & 31;
    int beg = rowptr[node], end = rowptr[node + 1];
    float4 ad = *(const float4*)(adst + node * 4);
    float acc[4][4] = {};
    float exsum[4] = {};
    for (int base = beg; base < end; base += 32) {
        int j = base + lane;
        if (j < end) {
            int sv = __ldg(srcs + j);
            float4 as = *(const float4*)(asrc + sv * 4);
            float v;
            float4 ex;
            v = as.x + ad.x; v = v > 0.f ? v : v * NEG_SLOPE; ex.x = __expf(v);
            v = as.y + ad.y; v = v > 0.f ? v : v * NEG_SLOPE; ex.y = __expf(v);
            v = as.z + ad.z; v = v > 0.f ? v : v * NEG_SLOPE; ex.z = __expf(v);
            v = as.w + ad.w; v = v > 0.f ? v : v * NEG_SLOPE; ex.w = __expf(v);
            sm_s[wslot][lane]  = sv;
            sm_ex[wslot][lane] = ex;
        }
        __syncwarp();
        int m = min(32, end - base);
        for (int t = 0; t < m; t++) {
            int    s  = sm_s[wslot][t];
            float4 ex = sm_ex[wslot][t];
            exsum[0] += ex.x; exsum[1] += ex.y; exsum[2] += ex.z; exsum[3] += ex.w;
            float4 v = __ldg((const float4*)(x + (long)s * FIN + lane * 4));
            acc[0][0] += ex.x * v.x; acc[0][1] += ex.x * v.y;
            acc[0][2] += ex.x * v.z; acc[0][3] += ex.x * v.w;
            acc[1][0] += ex.y * v.x; acc[1][1] += ex.y * v.y;
            acc[1][2] += ex.y * v.z; acc[1][3] += ex.y * v.w;
            acc[2][0] += ex.z * v.x; acc[2][1] += ex.z * v.y;
            acc[2][2] += ex.z * v.z; acc[2][3] += ex.z * v.w;
            acc[3][0] += ex.w * v.x; acc[3][1] += ex.w * v.y;
            acc[3][2] += ex.w * v.z; acc[3][3] += ex.w * v.w;
        }
        __syncwarp();
    }
    float* o = aggx + (long)node * DAGG + lane * 4;
    #pragma unroll
    for (int h = 0; h < 4; h++) {
        float inv = 1.f / exsum[h];
        uint4 u = make_uint4(f2tf(acc[h][0] * inv), f2tf(acc[h][1] * inv),
                             f2tf(acc[h][2] * inv), f2tf(acc[h][3] * inv));
        *(uint4*)(o + h * FIN) = u;
    }
}

// ================= fused GEMM1 + ELU(b1) + GEMM2 =============================
// Per 128-node block: for each head h, T = aggx_h @ W1_h (tf32 MMA), then
// ELU(T + b1_h) -> Ts (tf32 bits in smem), then acc2 += Ts @ W2[h*64:,:].
struct FusedSmem {
    uint32_t As[128][36];
    uint32_t Bs[32][72];
    uint32_t Ts[128][68];
    uint32_t Bs2[64][72];
    float    b1s[64];
};

__global__ __launch_bounds__(256) void fused_gemm12(
    const float* __restrict__ A,     // aggx (tf32 bits), lda DAGG
    const float* __restrict__ W1,    // ldb D1
    const float* __restrict__ b1,
    const float* __restrict__ W2,    // ldb D2
    float* __restrict__ C,           // xl2, ldc D2
    int M) {
    extern __shared__ char smem_raw[];
    FusedSmem& S = *reinterpret_cast<FusedSmem*>(smem_raw);
    int tid = threadIdx.x, lane = tid & 31, wid = tid >> 5;
    int wm = wid >> 1, wn = wid & 1;
    int row0 = blockIdx.y * 128;
    float acc2[2][4][4] = {};

    for (int h = 0; h < H1; h++) {
        const float* Ah = A + h * FIN;
        const float* Bh = W1 + h * 64;
        float acc1[2][4][4] = {};
        // ---- stage 1: T = aggx_h @ W1_h ----
        for (int k0 = 0; k0 < FIN; k0 += 32) {
            __syncthreads();
            {   // A tile 128x32 (already tf32 bits; raw copy)
                int r = tid >> 1, kc = (tid & 1) * 16;
                int gr = row0 + r;
                #pragma unroll
                for (int i = 0; i < 4; i++) {
                    uint4 u = make_uint4(0u, 0u, 0u, 0u);
                    if (gr < M)
                        u = *(const uint4*)(Ah + (long)gr * DAGG + k0 + kc + i * 4);
                    *(uint4*)(&S.As[r][kc + i * 4]) = u;
                }
            }
            {   // B tile 32x64 from W1 (cvt)
                int k = tid >> 3, n0 = (tid & 7) * 8;
                #pragma unroll
                for (int i = 0; i < 2; i++) {
                    float4 v = *(const float4*)(Bh + (long)(k0 + k) * D1 + n0 + i * 4);
                    *(uint4*)(&S.Bs[k][n0 + i * 4]) =
                        make_uint4(f2tf(v.x), f2tf(v.y), f2tf(v.z), f2tf(v.w));
                }
            }
            if (k0 == 0 && tid < 64) S.b1s[tid] = b1[h * 64 + tid];
            __syncthreads();
            #pragma unroll
            for (int k8 = 0; k8 < 4; k8++) {
                int kb = k8 * 8;
                uint32_t a[2][4];
                #pragma unroll
                for (int mt = 0; mt < 2; mt++) {
                    int row = wm * 32 + mt * 16 + (lane >> 2);
                    int col = kb + (lane & 3);
                    a[mt][0] = S.As[row][col];
                    a[mt][1] = S.As[row + 8][col];
                    a[mt][2] = S.As[row][col + 4];
                    a[mt][3] = S.As[row + 8][col + 4];
                }
                uint32_t b[4][2];
                #pragma unroll
                for (int nt = 0; nt < 4; nt++) {
                    int kk = kb + (lane & 3);
                    int nn = wn * 32 + nt * 8 + (lane >> 2);
                    b[nt][0] = S.Bs[kk][nn];
                    b[nt][1] = S.Bs[kk + 4][nn];
                }
                #pragma unroll
                for (int mt = 0; mt < 2; mt++)
                    #pragma unroll
                    for (int nt = 0; nt < 4; nt++)
                        mma_tf32(acc1[mt][nt], a[mt], b[nt]);
            }
        }
        __syncthreads();   // all reads of As/Bs + b1s done
        // ---- ELU(T + b1) -> Ts (tf32 bits) ----
        #pragma unroll
        for (int mt = 0; mt < 2; mt++) {
            #pragma unroll
            for (int nt = 0; nt < 4; nt++) {
                int r0 = wm * 32 + mt * 16 + (lane >> 2);
                int c0 = wn * 32 + nt * 8 + (lane & 3) * 2;
                #pragma unroll
                for (int i = 0; i < 2; i++) {
                    float v0 = acc1[mt][nt][i]     + S.b1s[c0 + i];
                    float v1 = acc1[mt][nt][i + 2] + S.b1s[c0 + i];
                    v0 = v0 > 0.f ? v0 : (__expf(v0) - 1.f);
                    v1 = v1 > 0.f ? v1 : (__expf(v1) - 1.f);
                    S.Ts[r0][c0 + i]     = f2tf(v0);
                    S.Ts[r0 + 8][c0 + i] = f2tf(v1);
                }
            }
        }
        {   // Bs2: W2 rows h*64..h*64+63, all 64 cols
            int r = tid >> 2, c = (tid & 3) * 16;
            #pragma unroll
            for (int i = 0; i < 4; i++) {
                float4 v = *(const float4*)(W2 + (long)(h * 64 + r) * D2 + c + i * 4);
                *(uint4*)(&S.Bs2[r][c + i * 4]) =
                    make_uint4(f2tf(v.x), f2tf(v.y), f2tf(v.z), f2tf(v.w));
            }
        }
        __syncthreads();
        // ---- stage 2: acc2 += Ts @ Bs2 (K = 64) ----
        #pragma unroll
        for (int k8 = 0; k8 < 8; k8++) {
            int kb = k8 * 8;
            uint32_t a[2][4];
            #pragma unroll
            for (int mt = 0; mt < 2; mt++) {
                int row = wm * 32 + mt * 16 + (lane >> 2);
                int col = kb + (lane & 3);
                a[mt][0] = S.Ts[row][col];
                a[mt][1] = S.Ts[row + 8][col];
                a[mt][2] = S.Ts[row][col + 4];
                a[mt][3] = S.Ts[row + 8][col + 4];
            }
            uint32_t b[4][2];
            #pragma unroll
            for (int nt = 0; nt < 4; nt++) {
                int kk = kb + (lane & 3);
                int nn = wn * 32 + nt * 8 + (lane >> 2);
                b[nt][0] = S.Bs2[kk][nn];
                b[nt][1] = S.Bs2[kk + 4][nn];
            }
            #pragma unroll
            for (int mt = 0; mt < 2; mt++)
                #pragma unroll
                for (int nt = 0; nt < 4; nt++)
                    mma_tf32(acc2[mt][nt], a[mt], b[nt]);
        }
        __syncthreads();   // before next head overwrites Ts/Bs2
    }
    // ---- store xl2 ----
    #pragma unroll
    for (int mt = 0; mt < 2; mt++) {
        #pragma unroll
        for (int nt = 0; nt < 4; nt++) {
            int r0 = row0 + wm * 32 + mt * 16 + (lane >> 2);
            int c0 = wn * 32 + nt * 8 + (lane & 3) * 2;
            if (r0 < M)
                *(float2*)(C + (long)r0 * D2 + c0) =
                    make_float2(acc2[mt][nt][0], acc2[mt][nt][1]);
            if (r0 + 8 < M)
                *(float2*)(C + (long)(r0 + 8) * D2 + c0) =
                    make_float2(acc2[mt][nt][2], acc2[mt][nt][3]);
        }
    }
}

// ================= gather layer2 (writes final d_out) ========================
__global__ __launch_bounds__(256) void gather2_kernel(
    const int* __restrict__ rowptr, const int* __restrict__ srcs,
    const float* __restrict__ asrc, const float* __restrict__ adst,
    const float* __restrict__ xl, const float* __restrict__ b2,
    float* __restrict__ out) {
    int node = blockIdx.x * 8 + (threadIdx.x >> 5);
    if (node >= NNODES) return;
    int lane = threadIdx.x & 31;
    int beg = rowptr[node], end = rowptr[node + 1];
    float adv = adst[node];
    float acc0 = 0.f, acc1 = 0.f, exsum = 0.f;
    for (int base = beg; base < end; base += 32) {
        int j = base + lane;
        int sv = 0;
        float exv = 0.f;
        if (j < end) {
            sv = __ldg(srcs + j);
            float v = __ldg(asrc + sv) + adv;
            v = v > 0.f ? v : v * NEG_SLOPE;
            exv = __expf(v);
        }
        int m = min(32, end - base);
        for (int t = 0; t < m; t++) {
            int   s  = __shfl_sync(0xFFFFFFFFu, sv,  t);
            float ex = __shfl_sync(0xFFFFFFFFu, exv, t);
            exsum += ex;
            acc0 += ex * __ldg(xl + (long)s * D2 + lane);
            acc1 += ex * __ldg(xl + (long)s * D2 + lane + 32);
        }
    }
    float inv = 1.f / exsum;
    out[(long)node * D2 + lane]      = acc0 * inv + b2[lane];
    out[(long)node * D2 + lane + 32] = acc1 * inv + b2[lane + 32];
}

// ================= launch ====================================================
extern "C" void kernel_launch(void* const* d_in, const int* in_sizes, int n_in,
                              void* d_out, int out_size) {
    const float* x     = (const float*)d_in[0];
    const int*   ei    = (const int*)d_in[1];
    const float* W1    = (const float*)d_in[2];
    const float* at_s1 = (const float*)d_in[3];
    const float* at_d1 = (const float*)d_in[4];
    const float* b1    = (const float*)d_in[5];
    const float* W2    = (const float*)d_in[6];
    const float* at_s2 = (const float*)d_in[7];
    const float* at_d2 = (const float*)d_in[8];
    const float* b2    = (const float*)d_in[9];
    float* out = (float*)d_out;

    float *aggx, *xl2, *ws1, *wd1, *as1, *ad1, *as2, *ad2;
    int *cnt, *rowptr, *wptr, *bsum, *boff, *srcs;
    cudaGetSymbolAddress((void**)&aggx,   g_aggx);
    cudaGetSymbolAddress((void**)&xl2,    g_xl2);
    cudaGetSymbolAddress((void**)&ws1,    g_ws1);
    cudaGetSymbolAddress((void**)&wd1,    g_wd1);
    cudaGetSymbolAddress((void**)&as1,    g_as1);
    cudaGetSymbolAddress((void**)&ad1,    g_ad1);
    cudaGetSymbolAddress((void**)&as2,    g_as2);
    cudaGetSymbolAddress((void**)&ad2,    g_ad2);
    cudaGetSymbolAddress((void**)&cnt,    g_cnt);
    cudaGetSymbolAddress((void**)&rowptr, g_rowptr);
    cudaGetSymbolAddress((void**)&wptr,   g_wptr);
    cudaGetSymbolAddress((void**)&bsum,   g_bsum);
    cudaGetSymbolAddress((void**)&boff,   g_boff);
    cudaGetSymbolAddress((void**)&srcs,   g_srcs);

    cudaFuncSetAttribute(fused_gemm12,
                         cudaFuncAttributeMaxDynamicSharedMemorySize,
                         (int)sizeof(FusedSmem));

    // ---- CSR build (by dst) ----
    zero_cnt<<<(NNODES + 255) / 256, 256>>>(cnt);
    hist_kernel<<<(ETOT + 255) / 256, 256>>>(ei, cnt);
    scan1_kernel<<<NBLK_SCAN, 256>>>(cnt, rowptr, bsum);
    scan2_kernel<<<1, 256>>>(bsum, boff);
    scan3_kernel<<<(NNODES + 255) / 256, 256>>>(rowptr, boff, wptr);
    scatter_kernel<<<(ETOT + 255) / 256, 256>>>(ei, wptr, srcs);

    // ---- layer 1 ----
    w1prep_kernel<<<1, 512>>>(W1, at_s1, at_d1, ws1, wd1);
    alpha1_kernel<<<(NNODES * 32 + 255) / 256, 256>>>(x, ws1, wd1, as1, ad1);
    gather1_kernel<<<(NNODES + 7) / 8, 256>>>(rowptr, srcs, as1, ad1, x, aggx);

    // ---- fused GEMM1 + ELU + GEMM2 ----
    fused_gemm12<<<dim3(1, (NNODES + 127) / 128), 256, sizeof(FusedSmem)>>>(
        aggx, W1, b1, W2, xl2, NNODES);

    // ---- layer 2 softmax + gather ----
    alpha2_kernel<<<(NNODES * 32 + 255) / 256, 256>>>(xl2, at_s2, at_d2, as2, ad2);
    gather2_kernel<<<(NNODES + 7) / 8, 256>>>(rowptr, srcs, as2, ad2, xl2, b2, out);
}